// round 13
// baseline (speedup 1.0000x reference)
#include <cuda_runtime.h>
#include <cstdint>

// ConditionalSplineSQ2D: out[b] = sum_{g,h,c} param[b,g,h,ii]*param[b,g,h,jj]*coef[g,h,c]
// B=4096, G*G=961 cells, P=8, C=36. Pure HBM stream: 126MB read once.
//
// 12-round invariant: DRAM% pinned at ~52 because each warp had exactly ONE
// 1KB slab outstanding (regfile full: 36 coef + 8 load + 8 compute = 64).
// Throughput identity: 32 warps x 1KB / ~2000cyc loaded latency = 16 B/cyc/SM.
// Fix: TWO independent register load buffers (A,B). Consume A -> reissue A's
// load (b+2) -> consume B -> reissue B (b+3): both slabs are in flight
// together during the stall, doubling outstanding bytes to ~62KB/SM, which
// doubles per-SM DRAM throughput to ~30 B/cyc (the DRAM floor). Funded by
// deleting the mov-double-buffer, prefetch pointers, and stagger temps.
// Epilogue: warp-reduce + part[k][warp] STS per b, one barrier at the end.

#define GG    961
#define CC    36
#define NTHR  992
#define NWARP 31
#define MAXK  28

__global__ __launch_bounds__(NTHR, 1)
void sq2d_kernel(const float* __restrict__ param,
                 const float* __restrict__ coef,
                 float* __restrict__ out,
                 int nB, int stride)
{
    __shared__ float part[MAXK * 32];   // [k][warp]

    const int tid  = threadIdx.x;
    const int lane = tid & 31;
    const int warp = tid >> 5;
    const bool active = (tid < GG);
    const int cell = active ? tid : (GG - 1);   // pad threads dup cell 960

    // 36 coefficients in registers (0 for pad threads).
    float cf[CC];
#pragma unroll
    for (int c = 0; c < CC; c++)
        cf[c] = active ? coef[cell * CC + c] : 0.0f;

    const int bid = blockIdx.x;
    const int K = (nB - bid + stride - 1) / stride;   // <= 27 b's per CTA

    const char* base0 = (const char*)param + (size_t)cell * 32
                      + (size_t)bid * (size_t)GG * 32;
    // 32-bit offsets: whole tensor is 126MB < 4GB.
    const uint32_t bstep = (uint32_t)((size_t)GG * 32 * (size_t)stride);
    const uint32_t wrap  = (uint32_t)K * bstep;

    // Staggered (even) start within this CTA's b-list.
    int k0 = ((warp * K) / NWARP) & ~1;
    if (k0 >= K) k0 = 0;

    uint32_t offL = (uint32_t)k0 * bstep;     // next load offset
    int kc = k0;                               // next consume slot

    float A0,A1,A2,A3,A4,A5,A6,A7, B0,B1,B2,B3,B4,B5,B6,B7;

    // Prefill: A <- slot k0, B <- slot k0+1 (K>=2 always here).
    {
        const char* p = base0 + offL;
        asm volatile("ld.global.nc.v4.f32 {%0,%1,%2,%3}, [%4];"
                     : "=f"(A0),"=f"(A1),"=f"(A2),"=f"(A3) : "l"(p));
        asm volatile("ld.global.nc.v4.f32 {%0,%1,%2,%3}, [%4+16];"
                     : "=f"(A4),"=f"(A5),"=f"(A6),"=f"(A7) : "l"(p));
        offL += bstep; if (offL >= wrap) offL = 0;
        const char* q = base0 + offL;
        asm volatile("ld.global.nc.v4.f32 {%0,%1,%2,%3}, [%4];"
                     : "=f"(B0),"=f"(B1),"=f"(B2),"=f"(B3) : "l"(q));
        asm volatile("ld.global.nc.v4.f32 {%0,%1,%2,%3}, [%4+16];"
                     : "=f"(B4),"=f"(B5),"=f"(B6),"=f"(B7) : "l"(q));
        offL += bstep; if (offL >= wrap) offL = 0;
    }

#pragma unroll 1
    for (int j = 0; j + 1 < K; j += 2) {
        // ---- consume A (slot kc) ----
        float accA;
        {
            float pv[8] = { A0,A1,A2,A3,A4,A5,A6,A7 };
            float acc = 0.0f;
            int c = 0;
#pragma unroll
            for (int i = 0; i < 8; i++) {
                float q = 0.0f;
#pragma unroll
                for (int jj = i; jj < 8; jj++)
                    q = fmaf(cf[c++], pv[jj], q);
                acc = fmaf(pv[i], q, acc);
            }
            accA = acc;
        }
        // Reissue A's load (slot kc+2) immediately -> overlaps with B's flight.
        if (j + 2 < K) {
            const char* p = base0 + offL;
            asm volatile("ld.global.nc.v4.f32 {%0,%1,%2,%3}, [%4];"
                         : "=f"(A0),"=f"(A1),"=f"(A2),"=f"(A3) : "l"(p));
            asm volatile("ld.global.nc.v4.f32 {%0,%1,%2,%3}, [%4+16];"
                         : "=f"(A4),"=f"(A5),"=f"(A6),"=f"(A7) : "l"(p));
        }
        offL += bstep; if (offL >= wrap) offL = 0;

        // ---- consume B (slot kc+1) ----
        float accB;
        {
            float pv[8] = { B0,B1,B2,B3,B4,B5,B6,B7 };
            float acc = 0.0f;
            int c = 0;
#pragma unroll
            for (int i = 0; i < 8; i++) {
                float q = 0.0f;
#pragma unroll
                for (int jj = i; jj < 8; jj++)
                    q = fmaf(cf[c++], pv[jj], q);
                acc = fmaf(pv[i], q, acc);
            }
            accB = acc;
        }
        if (j + 3 < K) {
            const char* p = base0 + offL;
            asm volatile("ld.global.nc.v4.f32 {%0,%1,%2,%3}, [%4];"
                         : "=f"(B0),"=f"(B1),"=f"(B2),"=f"(B3) : "l"(p));
            asm volatile("ld.global.nc.v4.f32 {%0,%1,%2,%3}, [%4+16];"
                         : "=f"(B4),"=f"(B5),"=f"(B6),"=f"(B7) : "l"(p));
        }
        offL += bstep; if (offL >= wrap) offL = 0;

        // ---- reductions (both shfl chains interleave for ILP) ----
#pragma unroll
        for (int o = 16; o > 0; o >>= 1) {
            accA += __shfl_xor_sync(0xffffffffu, accA, o);
            accB += __shfl_xor_sync(0xffffffffu, accB, o);
        }
        if (lane == 0) {
            const int kc1 = (kc + 1 < K) ? kc + 1 : 0;
            part[kc * 32 + warp]  = accA;
            part[kc1 * 32 + warp] = accB;
        }
        kc += 2; if (kc >= K) kc -= K;
    }

    // Tail (K odd): one more consume from A.
    if (K & 1) {
        float pv[8] = { A0,A1,A2,A3,A4,A5,A6,A7 };
        float acc = 0.0f;
        int c = 0;
#pragma unroll
        for (int i = 0; i < 8; i++) {
            float q = 0.0f;
#pragma unroll
            for (int jj = i; jj < 8; jj++)
                q = fmaf(cf[c++], pv[jj], q);
            acc = fmaf(pv[i], q, acc);
        }
#pragma unroll
        for (int o = 16; o > 0; o >>= 1)
            acc += __shfl_xor_sync(0xffffffffu, acc, o);
        if (lane == 0)
            part[kc * 32 + warp] = acc;
    }

    __syncthreads();   // the only block barrier

    // Warp w finalizes b = bid + w*stride.
    if (warp < K) {
        float v = (lane < NWARP) ? part[warp * 32 + lane] : 0.0f;
#pragma unroll
        for (int o = 16; o > 0; o >>= 1)
            v += __shfl_xor_sync(0xffffffffu, v, o);
        if (lane == 0)
            out[bid + warp * stride] = v;
    }
}

extern "C" void kernel_launch(void* const* d_in, const int* in_sizes, int n_in,
                              void* d_out, int out_size)
{
    const float* param = (const float*)d_in[0];   // [B, 31, 31, 8] f32
    const float* coef  = (const float*)d_in[1];   // [31, 31, 36]   f32
    float* out = (float*)d_out;                    // [B] f32

    const int nB = in_sizes[0] / (GG * 8);

    int dev = 0, sms = 0;
    cudaGetDevice(&dev);
    cudaDeviceGetAttribute(&sms, cudaDevAttrMultiProcessorCount, dev);
    if (sms <= 0) sms = 148;

    int grid = sms;
    const int min_grid = (nB + MAXK - 1) / MAXK;   // keep K <= MAXK
    if (grid < min_grid) grid = min_grid;
    if (grid > nB) grid = nB;

    sq2d_kernel<<<grid, NTHR>>>(param, coef, out, nB, grid);
}

// round 14
// speedup vs baseline: 1.4041x; 1.4041x over previous
#include <cuda_runtime.h>
#include <cstdint>

// ConditionalSplineSQ2D: out[b] = sum_{g,h,c} param[b,g,h,ii]*param[b,g,h,jj]*coef[g,h,c]
// B=4096, G*G=961 cells, P=8, C=36. Pure HBM stream: 126MB read once.
//
// Queueing identity: throughput/SM = outstanding_bytes / (577 + queue).
// 1KB/warp (all prior rounds) pins ~15.5 B/cyc/SM = the 4.2TB/s plateau.
// This round: TWO register load buffers per thread (A,B = 2KB/warp in
// flight) made to FIT 64 regs (R13 spilled):
//  - kernel templated on STRIDE (=grid): the inter-b byte step is a
//    compile-time immediate -> no wrap/limit/bstep registers, no in-loop ALU
//  - no stagger, no in-loop reduction (one raw STS to part[k][tid], R10's
//    best epilogue), no shfl in the loop, no prefetch hints
// In-loop live set ~58 regs. Consume A -> reissue A(k+2) -> consume B ->
// reissue B(k+3): both 1KB slabs overlap in flight every iteration.

#define GG    961
#define CC    36
#define NTHR  992
#define NWARP 31
#define MAXK  28
#define SMEM_DYN (MAXK * NTHR * 4)   // 111104 B partials

extern __shared__ float part[];      // [MAXK][NTHR]

template <int CSTRIDE>
__global__ __launch_bounds__(NTHR, 1)
void sq2d_kernel(const float* __restrict__ param,
                 const float* __restrict__ coef,
                 float* __restrict__ out,
                 int nB, int rstride)
{
    const int tid  = threadIdx.x;
    const bool active = (tid < GG);
    const int cell = active ? tid : (GG - 1);     // pad threads dup cell 960

    const int stride = (CSTRIDE > 0) ? CSTRIDE : rstride;
    // Compile-time (for CSTRIDE>0) byte step between this CTA's b's.
    const uint32_t bstep = (uint32_t)(GG * 32) * (uint32_t)stride;

    // 36 coefficients in registers (0 for pad threads).
    float cf[CC];
#pragma unroll
    for (int c = 0; c < CC; c++)
        cf[c] = active ? coef[cell * CC + c] : 0.0f;

    const int bid = blockIdx.x;
    const int K = (nB - bid + stride - 1) / stride;    // <= 27

    const char* ptr = (const char*)param + (size_t)cell * 32
                    + (size_t)bid * (size_t)GG * 32;

    float A0,A1,A2,A3,A4,A5,A6,A7, B0,B1,B2,B3,B4,B5,B6,B7;

    // Prefill A <- slot 0, B <- slot 1.
    asm volatile("ld.global.nc.v4.f32 {%0,%1,%2,%3}, [%4];"
                 : "=f"(A0),"=f"(A1),"=f"(A2),"=f"(A3) : "l"(ptr));
    asm volatile("ld.global.nc.v4.f32 {%0,%1,%2,%3}, [%4+16];"
                 : "=f"(A4),"=f"(A5),"=f"(A6),"=f"(A7) : "l"(ptr));
    if (K >= 2) {
        const char* q = ptr + bstep;
        asm volatile("ld.global.nc.v4.f32 {%0,%1,%2,%3}, [%4];"
                     : "=f"(B0),"=f"(B1),"=f"(B2),"=f"(B3) : "l"(q));
        asm volatile("ld.global.nc.v4.f32 {%0,%1,%2,%3}, [%4+16];"
                     : "=f"(B4),"=f"(B5),"=f"(B6),"=f"(B7) : "l"(q));
    }
    ptr += 2u * bstep;                 // next refill source (slot 2)

    float* prow = &part[tid];          // STS cursor, advances 2*NTHR per pair

#pragma unroll 1
    for (int j = 0; j + 1 < K; j += 2) {
        // ---- consume A (slot j) ----
        {
            float pv[8] = { A0,A1,A2,A3,A4,A5,A6,A7 };
            float acc = 0.0f;
            int c = 0;
#pragma unroll
            for (int i = 0; i < 8; i++) {
                float q = 0.0f;
#pragma unroll
                for (int jj = i; jj < 8; jj++)
                    q = fmaf(cf[c++], pv[jj], q);
                acc = fmaf(pv[i], q, acc);
            }
            prow[0] = acc;             // raw partial, no reduction
        }
        // Reissue A for slot j+2 (overlaps with B's flight + both computes).
        if (j + 2 < K) {
            asm volatile("ld.global.nc.v4.f32 {%0,%1,%2,%3}, [%4];"
                         : "=f"(A0),"=f"(A1),"=f"(A2),"=f"(A3) : "l"(ptr));
            asm volatile("ld.global.nc.v4.f32 {%0,%1,%2,%3}, [%4+16];"
                         : "=f"(A4),"=f"(A5),"=f"(A6),"=f"(A7) : "l"(ptr));
        }

        // ---- consume B (slot j+1) ----
        {
            float pv[8] = { B0,B1,B2,B3,B4,B5,B6,B7 };
            float acc = 0.0f;
            int c = 0;
#pragma unroll
            for (int i = 0; i < 8; i++) {
                float q = 0.0f;
#pragma unroll
                for (int jj = i; jj < 8; jj++)
                    q = fmaf(cf[c++], pv[jj], q);
                acc = fmaf(pv[i], q, acc);
            }
            prow[NTHR] = acc;
        }
        // Reissue B for slot j+3.
        if (j + 3 < K) {
            const char* q = ptr + bstep;
            asm volatile("ld.global.nc.v4.f32 {%0,%1,%2,%3}, [%4];"
                         : "=f"(B0),"=f"(B1),"=f"(B2),"=f"(B3) : "l"(q));
            asm volatile("ld.global.nc.v4.f32 {%0,%1,%2,%3}, [%4+16];"
                         : "=f"(B4),"=f"(B5),"=f"(B6),"=f"(B7) : "l"(q));
        }

        ptr  += 2u * bstep;
        prow += 2 * NTHR;
    }

    // Tail (K odd): final consume from A.
    if (K & 1) {
        float pv[8] = { A0,A1,A2,A3,A4,A5,A6,A7 };
        float acc = 0.0f;
        int c = 0;
#pragma unroll
        for (int i = 0; i < 8; i++) {
            float q = 0.0f;
#pragma unroll
            for (int jj = i; jj < 8; jj++)
                q = fmaf(cf[c++], pv[jj], q);
            acc = fmaf(pv[i], q, acc);
        }
        prow[0] = acc;
    }

    __syncthreads();   // the only block barrier

    // Warp w finalizes b = bid + w*stride: 31 coalesced LDS + warp shuffle.
    const int lane = tid & 31;
    const int warp = tid >> 5;
    if (warp < K) {
        const float* row = &part[warp * NTHR];
        float v = 0.0f;
#pragma unroll
        for (int g = 0; g < NWARP; g++)
            v += row[g * 32 + lane];
#pragma unroll
        for (int o = 16; o > 0; o >>= 1)
            v += __shfl_xor_sync(0xffffffffu, v, o);
        if (lane == 0)
            out[bid + warp * stride] = v;
    }
}

extern "C" void kernel_launch(void* const* d_in, const int* in_sizes, int n_in,
                              void* d_out, int out_size)
{
    const float* param = (const float*)d_in[0];   // [B, 31, 31, 8] f32
    const float* coef  = (const float*)d_in[1];   // [31, 31, 36]   f32
    float* out = (float*)d_out;                    // [B] f32

    const int nB = in_sizes[0] / (GG * 8);

    static int configured = -1;
    if (configured < 0) {
        cudaFuncSetAttribute(sq2d_kernel<152>,
                             cudaFuncAttributeMaxDynamicSharedMemorySize, SMEM_DYN);
        cudaFuncSetAttribute(sq2d_kernel<148>,
                             cudaFuncAttributeMaxDynamicSharedMemorySize, SMEM_DYN);
        cudaFuncSetAttribute(sq2d_kernel<0>,
                             cudaFuncAttributeMaxDynamicSharedMemorySize, SMEM_DYN);
        configured = 1;
    }

    int dev = 0, sms = 0;
    cudaGetDevice(&dev);
    cudaDeviceGetAttribute(&sms, cudaDevAttrMultiProcessorCount, dev);
    if (sms <= 0) sms = 148;

    int grid = sms;
    const int min_grid = (nB + MAXK - 1) / MAXK;   // keep K <= MAXK
    if (grid < min_grid) grid = min_grid;
    if (grid > nB) grid = nB;

    if (grid == 152)
        sq2d_kernel<152><<<grid, NTHR, SMEM_DYN>>>(param, coef, out, nB, grid);
    else if (grid == 148)
        sq2d_kernel<148><<<grid, NTHR, SMEM_DYN>>>(param, coef, out, nB, grid);
    else
        sq2d_kernel<0><<<grid, NTHR, SMEM_DYN>>>(param, coef, out, nB, grid);
}